// round 15
// baseline (speedup 1.0000x reference)
#include <cuda_runtime.h>
#include <cuda_fp16.h>
#include <math.h>

#define Bb 128
#define Ss 800
#define Hh 512
#define Ee 256
#define Vv 34
#define Tt 128
#define KVE (Bb * Ss * Hh)
#define K1d 1280
#define K2d 1024
// smem: W chunks [0, WB) | X staging / attn scratch [WB, DYNB)
#define WB 165888            // 36 chunks x 32 rows x 72 halves
#define XSTG 4608
#define NSTG 3
#define DYNB (WB + 4 * NSTG * XSTG)   // 221184

typedef unsigned int uint32;

// ---------------- persistent device buffers ----------------
__device__ __align__(16) __half g_kh[KVE];
__device__ __align__(16) __half g_vh[KVE];
__device__ __align__(16) __half g_W1h[2048 * K1d];
__device__ __align__(16) __half g_W2h[2048 * K2d];
__device__ __align__(16) __half g_X1h[(768 + 1024) * Bb];
__device__ __align__(16) __half g_X2h[(512 + 1024) * Bb];
__device__ __align__(16) float g_c0[Hh * Bb];
__device__ __align__(16) float g_c1[Hh * Bb];
__device__ __align__(16) float g_h1t[Bb * Hh];
__device__ __align__(16) float g_tail[Hh * Bb];
__device__ __align__(16) float g_energy[Bb * Ss];   // normalized softmax weights
__device__ int g_voff[Bb + 1];                      // prefix sums of len
__device__ int g_tok[Bb * Tt];
__device__ int g_len[Bb];
__device__ unsigned g_bar_count;
__device__ volatile unsigned g_bar_gen;

__device__ __forceinline__ float sigf(float x) { return 1.0f / (1.0f + expf(-x)); }

__device__ __forceinline__ void cp16(void* dst, const void* src) {
    unsigned d = (unsigned)__cvta_generic_to_shared(dst);
    asm volatile("cp.async.cg.shared.global [%0],[%1],16;\n" :: "r"(d), "l"(src));
}
__device__ __forceinline__ ulonglong4 ld_keep32(const void* p) {
    ulonglong4 v;
    asm volatile("ld.global.nc.L2::evict_last.v4.b64 {%0,%1,%2,%3},[%4];"
                 : "=l"(v.x), "=l"(v.y), "=l"(v.z), "=l"(v.w) : "l"(p));
    return v;
}
__device__ __forceinline__ void gridbar() {
    __syncthreads();
    if (threadIdx.x == 0) {
        __threadfence();
        unsigned gen = g_bar_gen;
        if (atomicAdd(&g_bar_count, 1u) == gridDim.x - 1) {
            g_bar_count = 0;
            __threadfence();
            g_bar_gen = gen + 1;
        } else {
            while (g_bar_gen == gen) { }
        }
    }
    __syncthreads();
}

// ---------------- single setup kernel ----------------
__global__ void k_setup(const void* dec, const void* lens,
                        const float* __restrict__ Wih1, const float* __restrict__ Whh1,
                        const float* __restrict__ Wih2, const float* __restrict__ Whh2,
                        const float* __restrict__ key, const float* __restrict__ value,
                        const float* __restrict__ emb) {
    int gtid = blockIdx.x * blockDim.x + threadIdx.x;
    int stride = gridDim.x * blockDim.x;
    int tid = threadIdx.x;

    const int* L = (const int*)lens;
    bool is64 = (L[1] == 0 && L[3] == 0 && L[5] == 0 && L[7] == 0);

    if (gtid == 0) { g_bar_count = 0; g_bar_gen = 0; }

    if (blockIdx.x == 0) {
        if (tid < Bb)
            g_len[tid] = is64 ? (int)((const long long*)lens)[tid] : L[tid];
        for (int i = tid; i < Bb * Tt; i += blockDim.x)
            g_tok[i] = is64 ? (int)((const long long*)dec)[i] : ((const int*)dec)[i];
        __syncthreads();
        if (tid == 0) {
            int acc = 0;
            for (int b = 0; b < Bb; b++) { g_voff[b] = acc; acc += g_len[b]; }
            g_voff[Bb] = acc;
        }
    }

    for (int i = gtid; i < 2048 * K1d; i += stride) {
        int r = i / K1d, k = i - r * K1d;
        int u = r >> 2, g = r & 3;
        int j = g * Hh + u;
        float w = (k < 768) ? Wih1[j * 768 + k] : Whh1[j * 512 + (k - 768)];
        g_W1h[i] = __float2half_rn(w);
    }
    for (int i = gtid; i < 2048 * K2d; i += stride) {
        int r = i / K2d, k = i - r * K2d;
        int u = r >> 2, g = r & 3;
        int j = g * Hh + u;
        float w = (k < 512) ? Wih2[j * 512 + k] : Whh2[j * 512 + (k - 512)];
        g_W2h[i] = __float2half_rn(w);
    }

    const float4* k4 = (const float4*)key;
    const float4* v4 = (const float4*)value;
    uint2* kh2 = (uint2*)g_kh;
    uint2* vh2 = (uint2*)g_vh;
    for (int i = gtid; i < KVE / 4; i += stride) {
        float4 kf = k4[i];
        half2 lo = __floats2half2_rn(kf.x, kf.y), hi = __floats2half2_rn(kf.z, kf.w);
        uint2 st; st.x = *(unsigned*)&lo; st.y = *(unsigned*)&hi;
        kh2[i] = st;
        float4 vf = v4[i];
        half2 lo2 = __floats2half2_rn(vf.x, vf.y), hi2 = __floats2half2_rn(vf.z, vf.w);
        uint2 sv; sv.x = *(unsigned*)&lo2; sv.y = *(unsigned*)&hi2;
        vh2[i] = sv;
    }

    for (int i = gtid; i < 1024 * Bb; i += stride) g_X1h[768 * Bb + i] = __float2half(0.f);
    for (int i = gtid; i < 1536 * Bb; i += stride) g_X2h[i] = __float2half(0.f);
    for (int idx = gtid; idx < Hh * Bb; idx += stride) {
        g_c0[idx] = 0.0f; g_c1[idx] = 0.0f; g_h1t[idx] = 0.0f;
        int b = idx & 127, h = idx >> 7;
        g_X1h[idx] = __float2half_rn(key[(size_t)b * Ss * Hh + h]);
    }
    for (int idx = gtid; idx < Ee * Bb; idx += stride) {
        int b = idx & 127, e = idx >> 7;
        long long tok = is64 ? ((const long long*)dec)[b * Tt] : (long long)((const int*)dec)[b * Tt];
        g_X1h[(512 + e) * Bb + b] = __float2half_rn(emb[(int)tok * Ee + e]);
    }
    for (int idx = gtid; idx < Hh * Bb; idx += stride) {
        int h = idx & 511, b = idx >> 9;
        int len = is64 ? (int)((const long long*)lens)[b] : L[b];
        float acc = 0.0f;
        const float* vb = value + (size_t)b * Ss * Hh + h;
        for (int s = len; s < Ss; s++) acc += vb[(size_t)s * Hh];
        g_tail[h * Bb + b] = acc;
    }
}

// ---------------- persistent mega-kernel ----------------
__global__ void __launch_bounds__(1024, 1) k_loop(
    const float* __restrict__ emb, const float* __restrict__ fcW,
    const float* __restrict__ fcb, const float* __restrict__ bias1,
    const float* __restrict__ bias2, float* __restrict__ out)
{
    extern __shared__ __align__(16) char dyn[];
    int tid = threadIdx.x;
    int blk = blockIdx.x;
    int rg = blk >> 1;
    int bh = blk & 1;
    int r0 = rg * 32;
    int bcol0 = bh * 64;

    // ---- preload W into smem (once) ----
    {
        __half* Wsm = (__half*)dyn;
        for (int i = tid; i < 36 * 32 * 8; i += 1024) {
            int chunk = i >> 8;
            int rem = i & 255;
            int row = rem >> 3, q = rem & 7;
            __half* dst = Wsm + chunk * 2304 + row * 72 + q * 8;
            const __half* src = (chunk < 20)
                ? g_W1h + (size_t)(r0 + row) * K1d + chunk * 64 + q * 8
                : g_W2h + (size_t)(r0 + row) * K2d + (chunk - 20) * 64 + q * 8;
            cp16(dst, src);
        }
        asm volatile("cp.async.commit_group;\ncp.async.wait_group 0;\n");
        __syncthreads();
    }

    // ---- lstm phase (unchanged from R13) ----
    auto lstm_phase = [&](int layer, int slot, const float* bias) {
        const __half* Xa = (layer == 1) ? g_X1h : g_X2h;
        const int split  = (layer == 1) ? 768 : 512;
        const int Kdim   = (layer == 1) ? K1d : K2d;
        const __half* Xb = Xa + (size_t)(split + slot * 512) * Bb;
        float* cst = (layer == 1) ? g_c0 : g_c1;
        const int chunkBase = (layer == 1) ? 0 : 20;

        int u0 = rg * 8;
        int wg = tid >> 8;
        int wt = tid & 255;
        int lane = wt & 31, w8 = wt >> 5;
        int rt = w8 >> 2;
        int ct = w8 & 3;
        int Kwg = Kdim >> 2;
        int wgK0 = wg * Kwg;
        int nst = Kwg >> 5;
        char* xb0 = dyn + WB + wg * NSTG * XSTG;

        float acc[2][4];
#pragma unroll
        for (int j = 0; j < 2; j++)
#pragma unroll
            for (int q = 0; q < 4; q++) acc[j][q] = 0.f;

        auto issue = [&](int st) {
            int k0 = wgK0 + st * 32;
            __half* sX = (__half*)(xb0 + (st % NSTG) * XSTG);
            const __half* xbase = ((k0 < split) ? (Xa + (size_t)k0 * Bb)
                                                : (Xb + (size_t)(k0 - split) * Bb)) + bcol0;
            int r = wt >> 3, q = wt & 7;
            cp16(sX + r * 72 + q * 8, xbase + r * Bb + q * 8);
            asm volatile("cp.async.commit_group;\n");
        };

        issue(0);
        issue(1);
        for (int st = 0; st < nst; st++) {
            if (st + 2 < nst) {
                issue(st + 2);
                asm volatile("cp.async.wait_group 2;\n");
            } else if (st + 1 < nst) {
                asm volatile("cp.async.wait_group 1;\n");
            } else {
                asm volatile("cp.async.wait_group 0;\n");
            }
            asm volatile("bar.sync %0, 256;" :: "r"(wg + 1) : "memory");

            int k0 = wgK0 + st * 32;
            __half* Wt = (__half*)dyn + (chunkBase + (k0 >> 6)) * 2304;
            __half* Xs = (__half*)(xb0 + (st % NSTG) * XSTG);
            unsigned aaddr = (unsigned)__cvta_generic_to_shared(
                Wt + (rt * 16 + (lane & 15)) * 72 + ((lane >> 4) * 8)) + (k0 & 32) * 2;
            unsigned bbase = (unsigned)__cvta_generic_to_shared(Xs + (lane & 15) * 72);

#pragma unroll
            for (int ki = 0; ki < 2; ki++) {
                int kc = ki * 16;
                uint32 ah[4];
                asm volatile("ldmatrix.sync.aligned.m8n8.x4.shared.b16 {%0,%1,%2,%3},[%4];"
                             : "=r"(ah[0]), "=r"(ah[1]), "=r"(ah[2]), "=r"(ah[3])
                             : "r"(aaddr + kc * 2));
#pragma unroll
                for (int j = 0; j < 2; j++) {
                    int n0 = ct * 16 + j * 8;
                    uint32 b0, b1;
                    asm volatile("ldmatrix.sync.aligned.m8n8.x2.trans.shared.b16 {%0,%1},[%2];"
                                 : "=r"(b0), "=r"(b1)
                                 : "r"(bbase + (kc * 72 + n0) * 2));
                    asm volatile("mma.sync.aligned.m16n8k16.row.col.f32.f16.f16.f32 "
                                 "{%0,%1,%2,%3},{%4,%5,%6,%7},{%8,%9},{%0,%1,%2,%3};"
                                 : "+f"(acc[j][0]), "+f"(acc[j][1]), "+f"(acc[j][2]), "+f"(acc[j][3])
                                 : "r"(ah[0]), "r"(ah[1]), "r"(ah[2]), "r"(ah[3]), "r"(b0), "r"(b1));
                }
            }
            asm volatile("bar.sync %0, 256;" :: "r"(wg + 1) : "memory");
        }

        __syncthreads();
        float* P = (float*)(dyn + WB);
#pragma unroll
        for (int j = 0; j < 2; j++) {
            int col = ct * 16 + j * 8 + (lane & 3) * 2;
            int row = rt * 16 + (lane >> 2);
            *(float2*)(P + wg * 2048 + row * 64 + col)       = make_float2(acc[j][0], acc[j][1]);
            *(float2*)(P + wg * 2048 + (row + 8) * 64 + col) = make_float2(acc[j][2], acc[j][3]);
        }
        __syncthreads();
        if (tid < 512) {
            int bl = tid & 63, ul = tid >> 6;
            int u = u0 + ul;
            int b = bcol0 + bl;
            float gv[4];
#pragma unroll
            for (int g = 0; g < 4; g++) {
                int r = (ul * 4 + g) * 64 + bl;
                gv[g] = P[r] + P[2048 + r] + P[4096 + r] + P[6144 + r] + bias[g * Hh + u];
            }
            float c = cst[u * Bb + b];
            float cn = sigf(gv[1]) * c + sigf(gv[0]) * tanhf(gv[2]);
            float h = sigf(gv[3]) * tanhf(cn);
            cst[u * Bb + b] = cn;
            __half hh = __float2half_rn(h);
            if (layer == 1) {
                g_X2h[u * Bb + b] = hh;
                g_X1h[(768 + (slot ^ 1) * 512 + u) * Bb + b] = hh;
            } else {
                g_X2h[(512 + (slot ^ 1) * 512 + u) * Bb + b] = hh;
                g_h1t[b * Hh + u] = h;
            }
        }
        __syncthreads();
    };

    // ---- attn smem (aliases X staging region, 55296 B available) ----
    char* abase = dyn + WB;
    float* sh1  = (float*)abase;             // 2048 B
    half2* sh1h = (half2*)(abase + 2048);    // 512 B
    float* sc   = (float*)(abase + 2560);    // 3200 B
    float* red  = (float*)(abase + 5760);    // 128 B
    float* sb2  = (float*)(abase + 5888);    // 8 B
    float* sctx = (float*)(abase + 6144);    // 8 x 512 floats = 16384 B
    int*   sVoff = (int*)(abase + 22528);    // 129 ints

    for (int t = 0; t < Tt; t++) {
        int slot = t & 1;
        lstm_phase(1, slot, bias1);
        gridbar();
        lstm_phase(2, slot, bias2);
        gridbar();

        // ============ SCORE phase: block = batch (fixed 800 rows) ==============
        {
            int b = blk;
            int lane = tid & 31, warp = tid >> 5;

            if (tid < Hh) sh1[tid] = __ldcg(&g_h1t[b * Hh + tid]);
            __syncthreads();
            if (tid < Hh / 2) sh1h[tid] = __floats2half2_rn(sh1[2 * tid], sh1[2 * tid + 1]);
            __syncthreads();

            half2 h1r[8];
            {
                uint4 a0 = ((const uint4*)sh1h)[lane * 2];
                uint4 a1 = ((const uint4*)sh1h)[lane * 2 + 1];
                h1r[0] = *(const half2*)&a0.x; h1r[1] = *(const half2*)&a0.y;
                h1r[2] = *(const half2*)&a0.z; h1r[3] = *(const half2*)&a0.w;
                h1r[4] = *(const half2*)&a1.x; h1r[5] = *(const half2*)&a1.y;
                h1r[6] = *(const half2*)&a1.z; h1r[7] = *(const half2*)&a1.w;
            }

            const char* kbase = (const char*)(g_kh + (size_t)b * Ss * Hh);
            for (int s = warp; s < Ss; s += 32) {
                ulonglong4 kv = ld_keep32(kbase + (size_t)s * 1024 + lane * 32);
                const half2* kp = (const half2*)&kv;
                float a = 0.0f;
#pragma unroll
                for (int j = 0; j < 8; j++) {
                    float2 kf = __half22float2(kp[j]);
                    float2 hf = __half22float2(h1r[j]);
                    a += kf.x * hf.x + kf.y * hf.y;
                }
#pragma unroll
                for (int o = 16; o; o >>= 1) a += __shfl_xor_sync(0xffffffffu, a, o);
                if (lane == 0) sc[s] = a;
            }
            __syncthreads();

            float m = (tid < Ss) ? sc[tid] : -3.4e38f;
#pragma unroll
            for (int o = 16; o; o >>= 1) m = fmaxf(m, __shfl_xor_sync(0xffffffffu, m, o));
            if (lane == 0) red[warp] = m;
            __syncthreads();
            if (warp == 0) {
                float v = red[lane];
#pragma unroll
                for (int o = 16; o; o >>= 1) v = fmaxf(v, __shfl_xor_sync(0xffffffffu, v, o));
                if (lane == 0) sb2[0] = v;
            }
            __syncthreads();
            float mx = sb2[0];
            float e = 0.0f;
            if (tid < Ss) e = expf(sc[tid] - mx);
            float su = e;
#pragma unroll
            for (int o = 16; o; o >>= 1) su += __shfl_xor_sync(0xffffffffu, su, o);
            __syncthreads();
            if (lane == 0) red[warp] = su;
            __syncthreads();
            if (warp == 0) {
                float v = red[lane];
#pragma unroll
                for (int o = 16; o; o >>= 1) v += __shfl_xor_sync(0xffffffffu, v, o);
                if (lane == 0) sb2[1] = v;
            }
            __syncthreads();
            float rinv = 1.0f / sb2[1];
            int len = g_len[b];

            // publish normalized energies; init ctx with masked-tail term
            if (tid < len) g_energy[b * Ss + tid] = e * rinv;
            if (tid < Hh)
                g_X1h[tid * Bb + b] = __float2half_rn(1e-9f * g_tail[tid * Bb + b]);

            // fc logits
            const float4* h14 = (const float4*)sh1;
            for (int v = warp; v < Vv; v += 32) {
                const float4* fw = (const float4*)(fcW + v * Hh);
                float a = 0.0f;
#pragma unroll
                for (int i = 0; i < 4; i++) {
                    float4 wv = fw[lane + 32 * i];
                    float4 hv = h14[lane + 32 * i];
                    a += wv.x * hv.x + wv.y * hv.y + wv.z * hv.z + wv.w * hv.w;
                }
#pragma unroll
                for (int o = 16; o; o >>= 1) a += __shfl_xor_sync(0xffffffffu, a, o);
                if (lane == 0) out[(size_t)b * (Tt * Vv) + t * Vv + v] = a + fcb[v];
            }

            // prefill embedding for next step
            if (t < Tt - 1 && tid < Ee) {
                int tok = g_tok[b * Tt + (t + 1)];
                g_X1h[(512 + tid) * Bb + b] = __float2half_rn(emb[tok * Ee + tid]);
            }
        }
        gridbar();

        // ============ VALUE phase: balanced global row walk, coalesced =========
        {
            if (tid <= Bb) sVoff[tid] = g_voff[tid];
            __syncthreads();
            int total = sVoff[Bb];
            int g0 = (blk * total) >> 7;
            int g1 = ((blk + 1) * total) >> 7;

            int b0 = 0;
            while (sVoff[b0 + 1] <= g0) b0++;
            int s = g0 - sVoff[b0];
            int remaining = g1 - g0;

            int c = tid & 127, part = tid >> 7;
            while (remaining > 0) {
                int len_b = sVoff[b0 + 1] - sVoff[b0];
                int seg = min(len_b - s, remaining);
                const char* vbase = (const char*)(g_vh + (size_t)b0 * Ss * Hh);
                const float* eb = g_energy + b0 * Ss;

                float accf[4] = {0.f, 0.f, 0.f, 0.f};
#pragma unroll 4
                for (int ss = s + part; ss < s + seg; ss += 8) {
                    float ee = __ldcg(eb + ss);
                    uint2 v = __ldcg((const uint2*)(vbase + (size_t)ss * 1024 + c * 8));
                    float2 f0 = __half22float2(*(const half2*)&v.x);
                    float2 f1 = __half22float2(*(const half2*)&v.y);
                    accf[0] += ee * f0.x; accf[1] += ee * f0.y;
                    accf[2] += ee * f1.x; accf[3] += ee * f1.y;
                }
                *(float4*)(sctx + part * Hh + c * 4) = make_float4(accf[0], accf[1], accf[2], accf[3]);
                __syncthreads();
                if (tid < Hh) {
                    float v = 0.0f;
#pragma unroll
                    for (int p = 0; p < 8; p++) v += sctx[p * Hh + tid];
                    atomicAdd((__half*)&g_X1h[tid * Bb + b0], __float2half_rn(v));
                }
                __syncthreads();
                remaining -= seg;
                s = 0;
                b0++;
            }
        }
        gridbar();
    }
}

// ---------------- host ----------------
extern "C" void kernel_launch(void* const* d_in, const int* in_sizes, int n_in,
                              void* d_out, int out_size) {
    const float* key   = (const float*)d_in[0];
    const float* value = (const float*)d_in[1];
    const void*  dec   = d_in[2];
    const void*  lens  = d_in[3];
    const float* emb   = (const float*)d_in[4];
    const float* Wih1  = (const float*)d_in[5];
    const float* Whh1  = (const float*)d_in[6];
    const float* b1    = (const float*)d_in[7];
    const float* Wih2  = (const float*)d_in[8];
    const float* Whh2  = (const float*)d_in[9];
    const float* b2    = (const float*)d_in[10];
    const float* fcW   = (const float*)d_in[11];
    const float* fcb   = (const float*)d_in[12];
    float* out = (float*)d_out;

    static bool attrSet = false;
    if (!attrSet) {
        cudaFuncSetAttribute(k_loop, cudaFuncAttributeMaxDynamicSharedMemorySize, DYNB);
        attrSet = true;
    }

    k_setup<<<2048, 256>>>(dec, lens, Wih1, Whh1, Wih2, Whh2, key, value, emb);
    k_loop<<<Bb, 1024, DYNB>>>(emb, fcW, fcb, b1, b2, out);
}

// round 16
// speedup vs baseline: 1.3310x; 1.3310x over previous
#include <cuda_runtime.h>
#include <cuda_fp16.h>
#include <math.h>

#define Bb 128
#define Ss 800
#define Hh 512
#define Ee 256
#define Vv 34
#define Tt 128
#define KVE (Bb * Ss * Hh)
#define K1d 1280
#define K2d 1024
// smem: W chunks [0, WB) | X staging / attn scratch [WB, DYNB)
// W chunk = 32 rows x 72 halves (64 k + 8 pad) = 4608 B; 36 chunks (20 W1 + 16 W2)
#define WB 165888
#define XSTG 4608            // one X stage: 32 k x 72 (64 b + 8 pad) halves
#define NSTG 3               // pipeline depth per warpgroup
#define DYNB (WB + 4 * NSTG * XSTG)   // 221184

typedef unsigned int uint32;

// ---------------- persistent device buffers ----------------
__device__ __align__(16) __half g_kh[KVE];
__device__ __align__(16) __half g_vh[KVE];
__device__ __align__(16) __half g_W1h[2048 * K1d];         // [r=u*4+g][k] fp16
__device__ __align__(16) __half g_W2h[2048 * K2d];
__device__ __align__(16) __half g_X1h[(768 + 1024) * Bb];  // ctx | emb | h0 x2 slots
__device__ __align__(16) __half g_X2h[(512 + 1024) * Bb];  // h0 | h1 x2 slots
__device__ __align__(16) float g_c0[Hh * Bb];
__device__ __align__(16) float g_c1[Hh * Bb];
__device__ __align__(16) float g_h1t[Bb * Hh];             // h1 fp32 [b][h]
__device__ __align__(16) float g_tail[Hh * Bb];
__device__ int g_tok[Bb * Tt];
__device__ int g_len[Bb];
__device__ unsigned g_bar_count;
__device__ volatile unsigned g_bar_gen;

__device__ __forceinline__ float sigf(float x) { return 1.0f / (1.0f + expf(-x)); }

__device__ __forceinline__ void cp16(void* dst, const void* src) {
    unsigned d = (unsigned)__cvta_generic_to_shared(dst);
    asm volatile("cp.async.cg.shared.global [%0],[%1],16;\n" :: "r"(d), "l"(src));
}

// 32-byte key load, keep-in-L2 hint (sm_103a requires v4.b64 for evict hints)
__device__ __forceinline__ ulonglong4 ld_keep32(const void* p) {
    ulonglong4 v;
    asm volatile("ld.global.nc.L2::evict_last.v4.b64 {%0,%1,%2,%3},[%4];"
                 : "=l"(v.x), "=l"(v.y), "=l"(v.z), "=l"(v.w) : "l"(p));
    return v;
}

__device__ __forceinline__ void gridbar() {
    __syncthreads();
    if (threadIdx.x == 0) {
        __threadfence();
        unsigned gen = g_bar_gen;
        if (atomicAdd(&g_bar_count, 1u) == gridDim.x - 1) {
            g_bar_count = 0;
            __threadfence();
            g_bar_gen = gen + 1;
        } else {
            while (g_bar_gen == gen) { }
        }
    }
    __syncthreads();
}

// ---------------- single setup kernel ----------------
__global__ void k_setup(const void* dec, const void* lens,
                        const float* __restrict__ Wih1, const float* __restrict__ Whh1,
                        const float* __restrict__ Wih2, const float* __restrict__ Whh2,
                        const float* __restrict__ key, const float* __restrict__ value,
                        const float* __restrict__ emb) {
    int gtid = blockIdx.x * blockDim.x + threadIdx.x;
    int stride = gridDim.x * blockDim.x;

    const int* L = (const int*)lens;
    bool is64 = (L[1] == 0 && L[3] == 0 && L[5] == 0 && L[7] == 0);

    if (gtid == 0) { g_bar_count = 0; g_bar_gen = 0; }
    if (blockIdx.x == 0) {
        for (int i = threadIdx.x; i < Bb; i += blockDim.x)
            g_len[i] = is64 ? (int)((const long long*)lens)[i] : L[i];
        const int* D = (const int*)dec;
        for (int i = threadIdx.x; i < Bb * Tt; i += blockDim.x)
            g_tok[i] = is64 ? (int)((const long long*)dec)[i] : D[i];
    }

    for (int i = gtid; i < 2048 * K1d; i += stride) {
        int r = i / K1d, k = i - r * K1d;
        int u = r >> 2, g = r & 3;
        int j = g * Hh + u;
        float w = (k < 768) ? Wih1[j * 768 + k] : Whh1[j * 512 + (k - 768)];
        g_W1h[i] = __float2half_rn(w);
    }
    for (int i = gtid; i < 2048 * K2d; i += stride) {
        int r = i / K2d, k = i - r * K2d;
        int u = r >> 2, g = r & 3;
        int j = g * Hh + u;
        float w = (k < 512) ? Wih2[j * 512 + k] : Whh2[j * 512 + (k - 512)];
        g_W2h[i] = __float2half_rn(w);
    }

    const float4* k4 = (const float4*)key;
    const float4* v4 = (const float4*)value;
    uint2* kh2 = (uint2*)g_kh;
    uint2* vh2 = (uint2*)g_vh;
    for (int i = gtid; i < KVE / 4; i += stride) {
        float4 kf = k4[i];
        half2 lo = __floats2half2_rn(kf.x, kf.y), hi = __floats2half2_rn(kf.z, kf.w);
        uint2 st; st.x = *(unsigned*)&lo; st.y = *(unsigned*)&hi;
        kh2[i] = st;
        float4 vf = v4[i];
        half2 lo2 = __floats2half2_rn(vf.x, vf.y), hi2 = __floats2half2_rn(vf.z, vf.w);
        uint2 sv; sv.x = *(unsigned*)&lo2; sv.y = *(unsigned*)&hi2;
        vh2[i] = sv;
    }

    for (int i = gtid; i < 1024 * Bb; i += stride) g_X1h[768 * Bb + i] = __float2half(0.f);
    for (int i = gtid; i < 1536 * Bb; i += stride) g_X2h[i] = __float2half(0.f);
    for (int idx = gtid; idx < Hh * Bb; idx += stride) {
        g_c0[idx] = 0.0f; g_c1[idx] = 0.0f; g_h1t[idx] = 0.0f;
        int b = idx & 127, h = idx >> 7;
        g_X1h[idx] = __float2half_rn(key[(size_t)b * Ss * Hh + h]);
    }
    for (int idx = gtid; idx < Ee * Bb; idx += stride) {
        int b = idx & 127, e = idx >> 7;
        long long tok = is64 ? ((const long long*)dec)[b * Tt] : (long long)((const int*)dec)[b * Tt];
        g_X1h[(512 + e) * Bb + b] = __float2half_rn(emb[(int)tok * Ee + e]);
    }
    for (int idx = gtid; idx < Hh * Bb; idx += stride) {
        int h = idx & 511, b = idx >> 9;
        int len = is64 ? (int)((const long long*)lens)[b] : L[b];
        float acc = 0.0f;
        const float* vb = value + (size_t)b * Ss * Hh + h;
        for (int s = len; s < Ss; s++) acc += vb[(size_t)s * Hh];
        g_tail[h * Bb + b] = acc;
    }
}

// ---------------- persistent mega-kernel ----------------
// 128 blocks x 1024 threads. Block = 32 W-rows (rg=blk>>1) x 64 batches (bh=blk&1).
// W resident in smem; X staged per 32-k chunk, 3-deep pipeline, 4 warpgroups split K.
__global__ void __launch_bounds__(1024, 1) k_loop(
    const float* __restrict__ emb, const float* __restrict__ fcW,
    const float* __restrict__ fcb, const float* __restrict__ bias1,
    const float* __restrict__ bias2, float* __restrict__ out)
{
    extern __shared__ __align__(16) char dyn[];
    int tid = threadIdx.x;
    int blk = blockIdx.x;
    int rg = blk >> 1;             // row-group (0..63): rows rg*32..+32, u0 = rg*8
    int bh = blk & 1;              // batch half
    int r0 = rg * 32;
    int bcol0 = bh * 64;

    // ---- preload W into smem (once): 36 chunks x 32 rows x 72 halves ----
    {
        __half* Wsm = (__half*)dyn;
        for (int i = tid; i < 36 * 32 * 8; i += 1024) {
            int chunk = i >> 8;
            int rem = i & 255;
            int row = rem >> 3, q = rem & 7;
            __half* dst = Wsm + chunk * 2304 + row * 72 + q * 8;
            const __half* src = (chunk < 20)
                ? g_W1h + (size_t)(r0 + row) * K1d + chunk * 64 + q * 8
                : g_W2h + (size_t)(r0 + row) * K2d + (chunk - 20) * 64 + q * 8;
            cp16(dst, src);
        }
        asm volatile("cp.async.commit_group;\ncp.async.wait_group 0;\n");
        __syncthreads();
    }

    // ---- lstm phase ----
    auto lstm_phase = [&](int layer, int slot, const float* bias) {
        const __half* Xa = (layer == 1) ? g_X1h : g_X2h;
        const int split  = (layer == 1) ? 768 : 512;
        const int Kdim   = (layer == 1) ? K1d : K2d;
        const __half* Xb = Xa + (size_t)(split + slot * 512) * Bb;
        float* cst = (layer == 1) ? g_c0 : g_c1;
        const int chunkBase = (layer == 1) ? 0 : 20;

        int u0 = rg * 8;
        int wg = tid >> 8;
        int wt = tid & 255;
        int lane = wt & 31, w8 = wt >> 5;
        int rt = w8 >> 2;            // row-tile 0/1 (16 rows each)
        int ct = w8 & 3;             // col-tile (16 batches each)
        int Kwg = Kdim >> 2;
        int wgK0 = wg * Kwg;
        int nst = Kwg >> 5;          // 10 (l1) or 8 (l2) stages of 32 k
        char* xb0 = dyn + WB + wg * NSTG * XSTG;

        float acc[2][4];
#pragma unroll
        for (int j = 0; j < 2; j++)
#pragma unroll
            for (int q = 0; q < 4; q++) acc[j][q] = 0.f;

        auto issue = [&](int st) {
            int k0 = wgK0 + st * 32;
            __half* sX = (__half*)(xb0 + (st % NSTG) * XSTG);
            const __half* xbase = ((k0 < split) ? (Xa + (size_t)k0 * Bb)
                                                : (Xb + (size_t)(k0 - split) * Bb)) + bcol0;
            int r = wt >> 3, q = wt & 7;   // 32 rows x 8 quads = 256 threads
            cp16(sX + r * 72 + q * 8, xbase + r * Bb + q * 8);
            asm volatile("cp.async.commit_group;\n");
        };

        issue(0);
        issue(1);
        for (int st = 0; st < nst; st++) {
            if (st + 2 < nst) {
                issue(st + 2);
                asm volatile("cp.async.wait_group 2;\n");
            } else if (st + 1 < nst) {
                asm volatile("cp.async.wait_group 1;\n");
            } else {
                asm volatile("cp.async.wait_group 0;\n");
            }
            asm volatile("bar.sync %0, 256;" :: "r"(wg + 1) : "memory");

            int k0 = wgK0 + st * 32;
            __half* Wt = (__half*)dyn + (chunkBase + (k0 >> 6)) * 2304;
            __half* Xs = (__half*)(xb0 + (st % NSTG) * XSTG);
            unsigned aaddr = (unsigned)__cvta_generic_to_shared(
                Wt + (rt * 16 + (lane & 15)) * 72 + ((lane >> 4) * 8)) + (k0 & 32) * 2;
            unsigned bbase = (unsigned)__cvta_generic_to_shared(Xs + (lane & 15) * 72);

#pragma unroll
            for (int ki = 0; ki < 2; ki++) {
                int kc = ki * 16;
                uint32 ah[4];
                asm volatile("ldmatrix.sync.aligned.m8n8.x4.shared.b16 {%0,%1,%2,%3},[%4];"
                             : "=r"(ah[0]), "=r"(ah[1]), "=r"(ah[2]), "=r"(ah[3])
                             : "r"(aaddr + kc * 2));
#pragma unroll
                for (int j = 0; j < 2; j++) {
                    int n0 = ct * 16 + j * 8;
                    uint32 b0, b1;
                    asm volatile("ldmatrix.sync.aligned.m8n8.x2.trans.shared.b16 {%0,%1},[%2];"
                                 : "=r"(b0), "=r"(b1)
                                 : "r"(bbase + (kc * 72 + n0) * 2));
                    asm volatile("mma.sync.aligned.m16n8k16.row.col.f32.f16.f16.f32 "
                                 "{%0,%1,%2,%3},{%4,%5,%6,%7},{%8,%9},{%0,%1,%2,%3};"
                                 : "+f"(acc[j][0]), "+f"(acc[j][1]), "+f"(acc[j][2]), "+f"(acc[j][3])
                                 : "r"(ah[0]), "r"(ah[1]), "r"(ah[2]), "r"(ah[3]), "r"(b0), "r"(b1));
                }
            }
            asm volatile("bar.sync %0, 256;" :: "r"(wg + 1) : "memory");
        }

        __syncthreads();
        float* P = (float*)(dyn + WB);  // [wg][32 rows][64 cols], aliases X staging
#pragma unroll
        for (int j = 0; j < 2; j++) {
            int col = ct * 16 + j * 8 + (lane & 3) * 2;
            int row = rt * 16 + (lane >> 2);
            *(float2*)(P + wg * 2048 + row * 64 + col)       = make_float2(acc[j][0], acc[j][1]);
            *(float2*)(P + wg * 2048 + (row + 8) * 64 + col) = make_float2(acc[j][2], acc[j][3]);
        }
        __syncthreads();
        if (tid < 512) {
            int bl = tid & 63, ul = tid >> 6;     // 8 u x 64 b
            int u = u0 + ul;
            int b = bcol0 + bl;
            float gv[4];
#pragma unroll
            for (int g = 0; g < 4; g++) {
                int r = (ul * 4 + g) * 64 + bl;
                gv[g] = P[r] + P[2048 + r] + P[4096 + r] + P[6144 + r] + bias[g * Hh + u];
            }
            float c = cst[u * Bb + b];
            float cn = sigf(gv[1]) * c + sigf(gv[0]) * tanhf(gv[2]);
            float h = sigf(gv[3]) * tanhf(cn);
            cst[u * Bb + b] = cn;
            __half hh = __float2half_rn(h);
            if (layer == 1) {
                g_X2h[u * Bb + b] = hh;
                g_X1h[(768 + (slot ^ 1) * 512 + u) * Bb + b] = hh;
            } else {
                g_X2h[(512 + (slot ^ 1) * 512 + u) * Bb + b] = hh;
                g_h1t[b * Hh + u] = h;
            }
        }
        __syncthreads();
    };

    // ---- attn smem (aliases X staging region, 55296 B available) ----
    char* abase = dyn + WB;
    float* sh1  = (float*)abase;             // 2048 B
    half2* sh1h = (half2*)(abase + 2048);    // 512 B
    float* sc   = (float*)(abase + 2560);    // 3200 B
    float* red  = (float*)(abase + 5760);    // 128 B
    float* sb2  = (float*)(abase + 5888);    // 8 B
    float* sctx = (float*)(abase + 6144);    // 16 parts x 512 floats = 32768 B

    for (int t = 0; t < Tt; t++) {
        int slot = t & 1;
        lstm_phase(1, slot, bias1);
        gridbar();
        lstm_phase(2, slot, bias2);
        gridbar();

        // ================= ATTN: block = batch =================
        {
            int b = blk;
            int lane = tid & 31, warp = tid >> 5;

            if (tid < Hh) sh1[tid] = __ldcg(&g_h1t[b * Hh + tid]);
            __syncthreads();
            if (tid < Hh / 2) sh1h[tid] = __floats2half2_rn(sh1[2 * tid], sh1[2 * tid + 1]);
            __syncthreads();

            // lane's h1 slice: h = lane*16 .. +16 (8 half2)
            half2 h1r[8];
            {
                uint4 a0 = ((const uint4*)sh1h)[lane * 2];
                uint4 a1 = ((const uint4*)sh1h)[lane * 2 + 1];
                h1r[0] = *(const half2*)&a0.x; h1r[1] = *(const half2*)&a0.y;
                h1r[2] = *(const half2*)&a0.z; h1r[3] = *(const half2*)&a0.w;
                h1r[4] = *(const half2*)&a1.x; h1r[5] = *(const half2*)&a1.y;
                h1r[6] = *(const half2*)&a1.z; h1r[7] = *(const half2*)&a1.w;
            }

            // ---- scores: one 32B keep-load per lane covers a full 1KB row/warp
            const char* kbase = (const char*)(g_kh + (size_t)b * Ss * Hh);
            for (int s = warp; s < Ss; s += 32) {
                ulonglong4 kv = ld_keep32(kbase + (size_t)s * 1024 + lane * 32);
                const half2* kp = (const half2*)&kv;
                float a = 0.0f;
#pragma unroll
                for (int j = 0; j < 8; j++) {
                    float2 kf = __half22float2(kp[j]);
                    float2 hf = __half22float2(h1r[j]);
                    a += kf.x * hf.x + kf.y * hf.y;
                }
#pragma unroll
                for (int o = 16; o; o >>= 1) a += __shfl_xor_sync(0xffffffffu, a, o);
                if (lane == 0) sc[s] = a;
            }
            __syncthreads();

            float m = (tid < Ss) ? sc[tid] : -3.4e38f;
#pragma unroll
            for (int o = 16; o; o >>= 1) m = fmaxf(m, __shfl_xor_sync(0xffffffffu, m, o));
            if (lane == 0) red[warp] = m;
            __syncthreads();
            if (warp == 0) {
                float v = red[lane];
#pragma unroll
                for (int o = 16; o; o >>= 1) v = fmaxf(v, __shfl_xor_sync(0xffffffffu, v, o));
                if (lane == 0) sb2[0] = v;
            }
            __syncthreads();
            float mx = sb2[0];
            float e = 0.0f;
            if (tid < Ss) { e = __expf(sc[tid] - mx); sc[tid] = e; }
            float su = e;
#pragma unroll
            for (int o = 16; o; o >>= 1) su += __shfl_xor_sync(0xffffffffu, su, o);
            __syncthreads();
            if (lane == 0) red[warp] = su;
            __syncthreads();
            if (warp == 0) {
                float v = red[lane];
#pragma unroll
                for (int o = 16; o; o >>= 1) v += __shfl_xor_sync(0xffffffffu, v, o);
                if (lane == 0) sb2[1] = v;
            }
            __syncthreads();
            float rinv = 1.0f / sb2[1];
            int len = g_len[b];

            // ---- ctx: 16 partitions x 64 lanes; each lane owns 8 h-values (16B)
            int c = tid & 63, part = tid >> 6;
            const char* vbase = (const char*)(g_vh + (size_t)b * Ss * Hh);
            float accf[8];
#pragma unroll
            for (int i = 0; i < 8; i++) accf[i] = 0.0f;
#pragma unroll 2
            for (int s = part; s < len; s += 16) {
                float ee = sc[s];
                uint4 v = __ldcg((const uint4*)(vbase + (size_t)s * 1024 + c * 16));
                const half2* vp = (const half2*)&v;
#pragma unroll
                for (int j = 0; j < 4; j++) {
                    float2 vf = __half22float2(vp[j]);
                    accf[2 * j]     += ee * vf.x;
                    accf[2 * j + 1] += ee * vf.y;
                }
            }
            {
                float4* dst = (float4*)(sctx + part * Hh + c * 8);
                dst[0] = make_float4(accf[0], accf[1], accf[2], accf[3]);
                dst[1] = make_float4(accf[4], accf[5], accf[6], accf[7]);
            }
            __syncthreads();
            if (tid < Hh) {
                float v = 0.0f;
#pragma unroll
                for (int p = 0; p < 16; p++) v += sctx[p * Hh + tid];
                float ctx = v * rinv + 1e-9f * g_tail[tid * Bb + b];
                g_X1h[tid * Bb + b] = __float2half_rn(ctx);
            }

            const float4* h14 = (const float4*)sh1;
            for (int v = warp; v < Vv; v += 32) {
                const float4* fw = (const float4*)(fcW + v * Hh);
                float a = 0.0f;
#pragma unroll
                for (int i = 0; i < 4; i++) {
                    float4 wv = fw[lane + 32 * i];
                    float4 hv = h14[lane + 32 * i];
                    a += wv.x * hv.x + wv.y * hv.y + wv.z * hv.z + wv.w * hv.w;
                }
#pragma unroll
                for (int o = 16; o; o >>= 1) a += __shfl_xor_sync(0xffffffffu, a, o);
                if (lane == 0) out[(size_t)b * (Tt * Vv) + t * Vv + v] = a + fcb[v];
            }

            if (t < Tt - 1 && tid < Ee) {
                int tok = g_tok[b * Tt + (t + 1)];
                g_X1h[(512 + tid) * Bb + b] = __float2half_rn(emb[tok * Ee + tid]);
            }
        }
        gridbar();
    }
}

// ---------------- host ----------------
extern "C" void kernel_launch(void* const* d_in, const int* in_sizes, int n_in,
                              void* d_out, int out_size) {
    const float* key   = (const float*)d_in[0];
    const float* value = (const float*)d_in[1];
    const void*  dec   = d_in[2];
    const void*  lens  = d_in[3];
    const float* emb   = (const float*)d_in[4];
    const float* Wih1  = (const float*)d_in[5];
    const float* Whh1  = (const float*)d_in[6];
    const float* b1    = (const float*)d_in[7];
    const float* Wih2  = (const float*)d_in[8];
    const float* Whh2  = (const float*)d_in[9];
    const float* b2    = (const float*)d_in[10];
    const float* fcW   = (const float*)d_in[11];
    const float* fcb   = (const float*)d_in[12];
    float* out = (float*)d_out;

    static bool attrSet = false;
    if (!attrSet) {
        cudaFuncSetAttribute(k_loop, cudaFuncAttributeMaxDynamicSharedMemorySize, DYNB);
        attrSet = true;
    }

    k_setup<<<2048, 256>>>(dec, lens, Wih1, Whh1, Wih2, Whh2, key, value, emb);
    k_loop<<<Bb, 1024, DYNB>>>(emb, fcW, fcb, b1, b2, out);
}